// round 2
// baseline (speedup 1.0000x reference)
#include <cuda_runtime.h>
#include <cstdint>

#define BB 512
#define SS 4096
#define DD 128
#define KK 409
#define VV 6
#define CS 4            // cluster size = chunks per row
#define CHUNK 1024      // tokens per CTA
#define TPT 4           // tokens per thread
#define NT 256          // threads per CTA

// ---------------------------------------------------------------------------
// helpers
// ---------------------------------------------------------------------------
__device__ __forceinline__ uint32_t smem_u32(const void* p) {
    uint32_t a;
    asm("{ .reg .u64 t; cvta.to.shared.u64 t, %1; cvt.u32.u64 %0, t; }" : "=r"(a) : "l"(p));
    return a;
}
__device__ __forceinline__ uint32_t ctarank() {
    uint32_t r; asm("mov.u32 %0, %%cluster_ctarank;" : "=r"(r)); return r;
}
// store 32-bit value into the same smem slot of cluster CTA `rank`
__device__ __forceinline__ void st_cluster_u32(uint32_t laddr, uint32_t rank, uint32_t val) {
    asm volatile("{ .reg .b32 ra; mapa.shared::cluster.u32 ra, %0, %1; st.shared::cluster.u32 [ra], %2; }"
                 :: "r"(laddr), "r"(rank), "r"(val) : "memory");
}
#define CLUSTER_ARRIVE() asm volatile("barrier.cluster.arrive.aligned;" ::: "memory")
#define CLUSTER_WAIT()   asm volatile("barrier.cluster.wait.aligned;"   ::: "memory")

// ---------------------------------------------------------------------------
// Fused kernel: 512 rows x 4 chunk-CTAs (cluster). Rank0 additionally computes
// the 6-class score/attention tables (V=6 makes every heavy tensor a LUT).
// ---------------------------------------------------------------------------
__global__ void __launch_bounds__(NT) __cluster_dims__(CS, 1, 1)
k_fused(const int* __restrict__ x,
        const float* __restrict__ emb,
        const float* __restrict__ W1, const float* __restrict__ b1,
        const float* __restrict__ W2, const float* __restrict__ b2,
        const float* __restrict__ W3, const float* __restrict__ b3,
        const float* __restrict__ A1, const float* __restrict__ a1,
        const float* __restrict__ A2, const float* __restrict__ a2,
        const float* __restrict__ C1, const float* __restrict__ c1,
        const float* __restrict__ C2, const float* __restrict__ c2,
        float* __restrict__ out) {
    const int row = blockIdx.x >> 2;
    const uint32_t rk = ctarank();
    const int tid = threadIdx.x;

    __shared__ float sc_s[VV];
    __shared__ float att_s[VV * DD];
    __shared__ float e_s[VV * DD];
    __shared__ float h1_s[VV * 64];
    __shared__ float h2_s[VV * 32];
    __shared__ float g_s[VV * 64];
    __shared__ int   pref[VV][NT];
    __shared__ int   cnt_mine[VV];
    __shared__ int   hist_all[CS][VV];
    __shared__ int   ls_all[CS][VV];
    __shared__ int   base_s[VV];
    __shared__ unsigned eqm_s[VV];
    __shared__ int   ls_mine[VV];
    __shared__ float pooled[DD];
    __shared__ float hbuf[64];

    float* __restrict__ pred_out = out;
    float* __restrict__ top_out  = out + BB;
    float* __restrict__ fs_out   = out + BB + (size_t)BB * KK;

    // ---- load my 4 tokens first (single LDG.128, front of the chain) ----
    const int4 tv = *reinterpret_cast<const int4*>(
        x + (size_t)row * SS + (size_t)rk * CHUNK + (size_t)tid * TPT);
    int tok[TPT] = {tv.x, tv.y, tv.z, tv.w};

    if (tid < VV) ls_mine[tid] = 0;

    // ---- rank0: score MLP on the 6 embedding rows (overlaps peers' work) ----
    if (rk == 0) {
        for (int i = tid; i < VV * DD; i += NT) e_s[i] = emb[i];
        __syncthreads();
        #pragma unroll
        for (int p = 0; p < 2; p++) {
            const int idx = p * NT + tid;
            if (idx < VV * 64) {
                const int cls = idx >> 6, n = idx & 63;
                const float* e = &e_s[cls * DD];
                float s0 = 0.f, s1 = 0.f, s2 = 0.f, s3 = 0.f;
                #pragma unroll
                for (int i = 0; i < DD; i += 4) {
                    s0 = fmaf(e[i + 0], W1[(i + 0) * 64 + n], s0);
                    s1 = fmaf(e[i + 1], W1[(i + 1) * 64 + n], s1);
                    s2 = fmaf(e[i + 2], W1[(i + 2) * 64 + n], s2);
                    s3 = fmaf(e[i + 3], W1[(i + 3) * 64 + n], s3);
                }
                h1_s[idx] = fmaxf((s0 + s1) + (s2 + s3) + b1[n], 0.f);
            }
        }
        __syncthreads();
        if (tid < VV * 32) {
            const int cls = tid >> 5, n = tid & 31;
            const float* h = &h1_s[cls * 64];
            float s0 = 0.f, s1 = 0.f;
            #pragma unroll
            for (int i = 0; i < 64; i += 2) {
                s0 = fmaf(h[i + 0], W2[(i + 0) * 32 + n], s0);
                s1 = fmaf(h[i + 1], W2[(i + 1) * 32 + n], s1);
            }
            h2_s[tid] = fmaxf(s0 + s1 + b2[n], 0.f);
        }
        __syncthreads();
        if (tid < VV * 32) {     // warp w (w<6) reduces class w
            const int cls = tid >> 5, l = tid & 31;
            float v = h2_s[tid] * W3[l];
            #pragma unroll
            for (int o = 16; o; o >>= 1) v += __shfl_down_sync(0xFFFFFFFFu, v, o);
            if (l == 0) sc_s[cls] = 1.f / (1.f + expf(-(v + b3[0])));
        }
    }

    // ---- per-thread histogram (score-independent) ----
    #pragma unroll
    for (int u = 0; u < VV; u++) {
        int c = 0;
        #pragma unroll
        for (int l = 0; l < TPT; l++) c += (tok[l] == u);
        pref[u][tid] = c;
    }
    __syncthreads();

    // ---- scan: warp v scans class v (8 elems per lane) ----
    {
        const int w = tid >> 5, lane = tid & 31;
        if (w < VV) {
            int vals[8]; int sum = 0;
            #pragma unroll
            for (int i = 0; i < 8; i++) { vals[i] = pref[w][lane * 8 + i]; sum += vals[i]; }
            int incl = sum;
            #pragma unroll
            for (int off = 1; off < 32; off <<= 1) {
                int n = __shfl_up_sync(0xFFFFFFFFu, incl, off);
                if (lane >= off) incl += n;
            }
            int excl = incl - sum;
            #pragma unroll
            for (int i = 0; i < 8; i++) { const int t = vals[i]; pref[w][lane * 8 + i] = excl; excl += t; }
            if (lane == 31) cnt_mine[w] = incl;
        }
    }
    __syncthreads();

    // ---- DSMEM exchange: my chunk counts -> all CTAs; rank0 -> sc broadcast ----
    if (tid < CS * VV) {
        const int target = tid / VV, v = tid % VV;
        st_cluster_u32(smem_u32(&hist_all[rk][v]), (uint32_t)target, (uint32_t)cnt_mine[v]);
    }
    if (rk == 0 && tid < (CS - 1) * VV) {
        const int target = 1 + tid / VV, v = tid % VV;
        st_cluster_u32(smem_u32(&sc_s[v]), (uint32_t)target, __float_as_uint(sc_s[v]));
    }
    CLUSTER_ARRIVE();
    CLUSTER_WAIT();

    // ---- final_scores writes (LUT, float4) ----
    {
        float4 f;
        f.x = sc_s[tok[0]]; f.y = sc_s[tok[1]]; f.z = sc_s[tok[2]]; f.w = sc_s[tok[3]];
        *reinterpret_cast<float4*>(fs_out + (size_t)row * SS + (size_t)rk * CHUNK + (size_t)tid * TPT) = f;
    }

    // ---- per-class rank base for this chunk (exact lax.top_k tie-break) ----
    if (tid < VV) {
        const float sv = sc_s[tid];
        int b = 0; unsigned m = 0;
        #pragma unroll
        for (int u = 0; u < VV; u++) {
            const float su = sc_s[u];
            const int tu = hist_all[0][u] + hist_all[1][u] + hist_all[2][u] + hist_all[3][u];
            if (su > sv) b += tu;
            if (su == sv) {
                m |= 1u << u;
                for (int r = 0; r < (int)rk; r++) b += hist_all[r][u];  // earlier chunks first
            }
        }
        base_s[tid] = b; eqm_s[tid] = m;
    }
    __syncthreads();

    // ---- ranked scatter + per-class selected counts ----
    {
        int P[VV];
        #pragma unroll
        for (int u = 0; u < VV; u++) P[u] = pref[u][tid];
        int rc[VV] = {0, 0, 0, 0, 0, 0};
        int ls[VV] = {0, 0, 0, 0, 0, 0};
        const size_t obase = (size_t)row * KK;
        const int gp0 = (int)rk * CHUNK + tid * TPT;
        #pragma unroll
        for (int l = 0; l < TPT; l++) {
            const int v = tok[l];
            const unsigned m = eqm_s[v];
            int r = base_s[v];
            #pragma unroll
            for (int u = 0; u < VV; u++)
                if ((m >> u) & 1u) r += P[u] + rc[u];
            #pragma unroll
            for (int u = 0; u < VV; u++) rc[u] += (v == u);
            if (r < KK) {
                top_out[obase + r] = (float)(gp0 + l);
                #pragma unroll
                for (int u = 0; u < VV; u++) ls[u] += (v == u);
            }
        }
        #pragma unroll
        for (int u = 0; u < VV; u++) {
            int s = ls[u];
            #pragma unroll
            for (int o = 16; o; o >>= 1) s += __shfl_down_sync(0xFFFFFFFFu, s, o);
            if ((tid & 31) == 0 && s) atomicAdd(&ls_mine[u], s);
        }
    }
    __syncthreads();

    // ---- push selected counts to rank0, then sync#2 (rank0 computes att
    //      table between arrive and wait -> fully overlapped) ----
    if (tid < VV)
        st_cluster_u32(smem_u32(&ls_all[rk][tid]), 0u, (uint32_t)ls_mine[tid]);
    CLUSTER_ARRIVE();

    if (rk == 0) {
        #pragma unroll
        for (int p = 0; p < 2; p++) {
            const int idx = p * NT + tid;
            if (idx < VV * 64) {
                const int cls = idx >> 6, n = idx & 63;
                const float* e = &e_s[cls * DD];
                float s0 = 0.f, s1 = 0.f, s2 = 0.f, s3 = 0.f;
                #pragma unroll
                for (int i = 0; i < DD; i += 4) {
                    s0 = fmaf(e[i + 0], A1[(i + 0) * 64 + n], s0);
                    s1 = fmaf(e[i + 1], A1[(i + 1) * 64 + n], s1);
                    s2 = fmaf(e[i + 2], A1[(i + 2) * 64 + n], s2);
                    s3 = fmaf(e[i + 3], A1[(i + 3) * 64 + n], s3);
                }
                g_s[idx] = fmaxf((s0 + s1) + (s2 + s3) + a1[n], 0.f);
            }
        }
        __syncthreads();
        #pragma unroll
        for (int p = 0; p < 3; p++) {
            const int idx = p * NT + tid;          // 0..767
            const int cls = idx >> 7, d = idx & 127;
            const float* g = &g_s[cls * 64];
            float s0 = 0.f, s1 = 0.f, s2 = 0.f, s3 = 0.f;
            #pragma unroll
            for (int j = 0; j < 64; j += 4) {
                s0 = fmaf(g[j + 0], A2[(j + 0) * DD + d], s0);
                s1 = fmaf(g[j + 1], A2[(j + 1) * DD + d], s1);
                s2 = fmaf(g[j + 2], A2[(j + 2) * DD + d], s2);
                s3 = fmaf(g[j + 3], A2[(j + 3) * DD + d], s3);
            }
            att_s[idx] = (s0 + s1) + (s2 + s3) + a2[d];
        }
    }
    CLUSTER_WAIT();

    // ---- rank0: pool + classify ----
    if (rk == 0) {
        __syncthreads();   // att_s writes + remote ls_all visible block-wide
        if (tid < DD) {
            float s = 0.f;
            #pragma unroll
            for (int v = 0; v < VV; v++) {
                const int cnt = ls_all[0][v] + ls_all[1][v] + ls_all[2][v] + ls_all[3][v];
                s = fmaf((float)cnt, att_s[v * DD + tid], s);
            }
            pooled[tid] = s / (float)KK;
        }
        __syncthreads();
        if (tid < 64) {
            float s0 = 0.f, s1 = 0.f;
            #pragma unroll
            for (int d = 0; d < DD; d += 2) {
                s0 = fmaf(pooled[d + 0], C1[(d + 0) * 64 + tid], s0);
                s1 = fmaf(pooled[d + 1], C1[(d + 1) * 64 + tid], s1);
            }
            hbuf[tid] = fmaxf(s0 + s1 + c1[tid], 0.f);
        }
        __syncthreads();
        if (tid == 0) {
            float s = c2[0];
            #pragma unroll
            for (int j = 0; j < 64; j++) s = fmaf(hbuf[j], C2[j], s);
            pred_out[row] = 1.f / (1.f + expf(-s));
        }
    }
}

// ---------------------------------------------------------------------------
// Launch: single fused kernel (cluster dims are compile-time)
// ---------------------------------------------------------------------------
extern "C" void kernel_launch(void* const* d_in, const int* in_sizes, int n_in,
                              void* d_out, int out_size) {
    const int*   x   = (const int*)  d_in[0];
    const float* emb = (const float*)d_in[1];
    const float* W1  = (const float*)d_in[2];
    const float* b1  = (const float*)d_in[3];
    const float* W2  = (const float*)d_in[4];
    const float* b2  = (const float*)d_in[5];
    const float* W3  = (const float*)d_in[6];
    const float* b3  = (const float*)d_in[7];
    const float* A1  = (const float*)d_in[8];
    const float* a1  = (const float*)d_in[9];
    const float* A2  = (const float*)d_in[10];
    const float* a2  = (const float*)d_in[11];
    const float* C1  = (const float*)d_in[12];
    const float* c1  = (const float*)d_in[13];
    const float* C2  = (const float*)d_in[14];
    const float* c2  = (const float*)d_in[15];
    float* out = (float*)d_out;

    k_fused<<<BB * CS, NT>>>(x, emb, W1, b1, W2, b2, W3, b3,
                             A1, a1, A2, a2, C1, c1, C2, c2, out);
}

// round 3
// speedup vs baseline: 3.9621x; 3.9621x over previous
#include <cuda_runtime.h>
#include <cstdint>

#define BB 512
#define SS 4096
#define DD 128
#define KK 409
#define VV 6
#define CS 4            // chunks per row
#define CHUNK 1024      // tokens per chunk-CTA
#define TPT 4           // tokens per thread
#define NT 256

// -------- global scratch (plain stores only; overwritten every run) --------
__device__ int   g_hist[BB][CS][VV];   // per-chunk class histograms
__device__ int   g_sel [BB][CS][VV];   // per-chunk selected-class counts
__device__ float g_sc  [VV];           // class scores
__device__ float g_att [VV * DD];      // class attention vectors

// ===========================================================================
// K1: blocks 0..2047 -> chunk histograms (pure bandwidth).
//     block 2048     -> all class tables (score MLP + attention MLP).
// ===========================================================================
__global__ void __launch_bounds__(NT)
k1_hist_tables(const int* __restrict__ x,
               const float* __restrict__ emb,
               const float* __restrict__ W1, const float* __restrict__ b1,
               const float* __restrict__ W2, const float* __restrict__ b2,
               const float* __restrict__ W3, const float* __restrict__ b3,
               const float* __restrict__ A1, const float* __restrict__ a1,
               const float* __restrict__ A2, const float* __restrict__ a2) {
    const int tid = threadIdx.x;

    if (blockIdx.x < BB * CS) {
        // ---------------- histogram block ----------------
        const int row = blockIdx.x >> 2, ch = blockIdx.x & 3;
        const int4 tv = *reinterpret_cast<const int4*>(
            x + (size_t)row * SS + (size_t)ch * CHUNK + (size_t)tid * TPT);
        const int tok[TPT] = {tv.x, tv.y, tv.z, tv.w};

        int c[VV];
        #pragma unroll
        for (int u = 0; u < VV; u++) {
            int s = 0;
            #pragma unroll
            for (int l = 0; l < TPT; l++) s += (tok[l] == u);
            c[u] = s;
        }
        // warp reduce 6 counters
        #pragma unroll
        for (int u = 0; u < VV; u++) {
            #pragma unroll
            for (int o = 16; o; o >>= 1) c[u] += __shfl_down_sync(0xFFFFFFFFu, c[u], o);
        }
        __shared__ int wsum[8][VV];
        const int w = tid >> 5, lane = tid & 31;
        if (lane == 0) {
            #pragma unroll
            for (int u = 0; u < VV; u++) wsum[w][u] = c[u];
        }
        __syncthreads();
        if (tid < VV) {
            int s = 0;
            #pragma unroll
            for (int i = 0; i < 8; i++) s += wsum[i][tid];
            g_hist[row][ch][tid] = s;
        }
        return;
    }

    // ---------------- table block ----------------
    __shared__ float e_s [VV * DD];
    __shared__ float h1_s[VV * 64];
    __shared__ float h2_s[VV * 32];
    __shared__ float g_s [VV * 64];

    for (int i = tid; i < VV * DD; i += NT) e_s[i] = emb[i];
    __syncthreads();

    // stage 1: importance h1 (384) + attention g (384)
    #pragma unroll
    for (int p = 0; p < 3; p++) {
        const int idx = p * NT + tid;
        const int half = idx >= VV * 64;
        const int j = half ? idx - VV * 64 : idx;
        const int cls = j >> 6, n = j & 63;
        const float* W  = half ? A1 : W1;
        const float* bv = half ? a1 : b1;
        const float* e = &e_s[cls * DD];
        float s0 = 0.f, s1 = 0.f, s2 = 0.f, s3 = 0.f;
        #pragma unroll
        for (int i = 0; i < DD; i += 4) {
            s0 = fmaf(e[i + 0], W[(i + 0) * 64 + n], s0);
            s1 = fmaf(e[i + 1], W[(i + 1) * 64 + n], s1);
            s2 = fmaf(e[i + 2], W[(i + 2) * 64 + n], s2);
            s3 = fmaf(e[i + 3], W[(i + 3) * 64 + n], s3);
        }
        const float r = fmaxf((s0 + s1) + (s2 + s3) + bv[n], 0.f);
        if (half) g_s[j] = r; else h1_s[j] = r;
    }
    __syncthreads();

    // stage 2: h2 (192 neurons)
    if (tid < VV * 32) {
        const int cls = tid >> 5, n = tid & 31;
        const float* h = &h1_s[cls * 64];
        float s0 = 0.f, s1 = 0.f;
        #pragma unroll
        for (int i = 0; i < 64; i += 2) {
            s0 = fmaf(h[i + 0], W2[(i + 0) * 32 + n], s0);
            s1 = fmaf(h[i + 1], W2[(i + 1) * 32 + n], s1);
        }
        h2_s[tid] = fmaxf(s0 + s1 + b2[n], 0.f);
    }
    __syncthreads();

    // attention table: 768 outputs
    #pragma unroll
    for (int p = 0; p < 3; p++) {
        const int idx = p * NT + tid;
        const int cls = idx >> 7, d = idx & 127;
        const float* g = &g_s[cls * 64];
        float s0 = 0.f, s1 = 0.f, s2 = 0.f, s3 = 0.f;
        #pragma unroll
        for (int j = 0; j < 64; j += 4) {
            s0 = fmaf(g[j + 0], A2[(j + 0) * DD + d], s0);
            s1 = fmaf(g[j + 1], A2[(j + 1) * DD + d], s1);
            s2 = fmaf(g[j + 2], A2[(j + 2) * DD + d], s2);
            s3 = fmaf(g[j + 3], A2[(j + 3) * DD + d], s3);
        }
        g_att[idx] = (s0 + s1) + (s2 + s3) + a2[d];
    }

    // scores: warp cls (cls<6) reduces h2[cls]·W3
    if (tid < VV * 32) {
        const int cls = tid >> 5, l = tid & 31;
        float v = h2_s[tid] * W3[l];
        #pragma unroll
        for (int o = 16; o; o >>= 1) v += __shfl_down_sync(0xFFFFFFFFu, v, o);
        if (l == 0) g_sc[cls] = 1.f / (1.f + expf(-(v + b3[0])));
    }
}

// ===========================================================================
// K2: 2048 chunk-CTAs. Scores LUT write, ranked top-k scatter, sel counts.
//     x is L2-resident from K1. Exact lax.top_k tie-break semantics.
// ===========================================================================
__global__ void __launch_bounds__(NT)
k2_rank(const int* __restrict__ x, float* __restrict__ out) {
    const int row = blockIdx.x >> 2, ch = blockIdx.x & 3;
    const int tid = threadIdx.x;

    __shared__ float sc_s[VV];
    __shared__ int   pref[VV][NT];
    __shared__ int   base_s[VV];
    __shared__ unsigned eqm_s[VV];
    __shared__ int   wls[8][VV];

    float* __restrict__ top_out = out + BB;
    float* __restrict__ fs_out  = out + BB + (size_t)BB * KK;

    if (tid < VV) sc_s[tid] = g_sc[tid];

    const int4 tv = *reinterpret_cast<const int4*>(
        x + (size_t)row * SS + (size_t)ch * CHUNK + (size_t)tid * TPT);
    const int tok[TPT] = {tv.x, tv.y, tv.z, tv.w};

    // per-thread histogram
    #pragma unroll
    for (int u = 0; u < VV; u++) {
        int c = 0;
        #pragma unroll
        for (int l = 0; l < TPT; l++) c += (tok[l] == u);
        pref[u][tid] = c;
    }
    __syncthreads();

    // final_scores (LUT, float4)
    {
        float4 f;
        f.x = sc_s[tok[0]]; f.y = sc_s[tok[1]]; f.z = sc_s[tok[2]]; f.w = sc_s[tok[3]];
        *reinterpret_cast<float4*>(fs_out + (size_t)row * SS + (size_t)ch * CHUNK
                                   + (size_t)tid * TPT) = f;
    }

    // warp v scans class v over the 256 thread-chunks (8 per lane)
    {
        const int w = tid >> 5, lane = tid & 31;
        if (w < VV) {
            int vals[8]; int sum = 0;
            #pragma unroll
            for (int i = 0; i < 8; i++) { vals[i] = pref[w][lane * 8 + i]; sum += vals[i]; }
            int incl = sum;
            #pragma unroll
            for (int off = 1; off < 32; off <<= 1) {
                int n = __shfl_up_sync(0xFFFFFFFFu, incl, off);
                if (lane >= off) incl += n;
            }
            int excl = incl - sum;
            #pragma unroll
            for (int i = 0; i < 8; i++) { const int t = vals[i]; pref[w][lane * 8 + i] = excl; excl += t; }
        }
    }

    // per-class rank base (strictly-greater totals + equal-score earlier-chunk prefix)
    if (tid < VV) {
        const float sv = sc_s[tid];
        int b = 0; unsigned m = 0;
        #pragma unroll
        for (int u = 0; u < VV; u++) {
            const float su = sc_s[u];
            int tu = 0;
            #pragma unroll
            for (int r = 0; r < CS; r++) tu += g_hist[row][r][u];
            if (su > sv) b += tu;
            if (su == sv) {
                m |= 1u << u;
                for (int r = 0; r < ch; r++) b += g_hist[row][r][u];
            }
        }
        base_s[tid] = b; eqm_s[tid] = m;
    }
    __syncthreads();

    // ranked scatter + per-class selected counts
    int ls[VV] = {0, 0, 0, 0, 0, 0};
    {
        int P[VV];
        #pragma unroll
        for (int u = 0; u < VV; u++) P[u] = pref[u][tid];
        int rc[VV] = {0, 0, 0, 0, 0, 0};
        const size_t obase = (size_t)row * KK;
        const int gp0 = ch * CHUNK + tid * TPT;
        #pragma unroll
        for (int l = 0; l < TPT; l++) {
            const int v = tok[l];
            const unsigned m = eqm_s[v];
            int r = base_s[v];
            #pragma unroll
            for (int u = 0; u < VV; u++)
                if ((m >> u) & 1u) r += P[u] + rc[u];
            #pragma unroll
            for (int u = 0; u < VV; u++) rc[u] += (v == u);
            if (r < KK) {
                top_out[obase + r] = (float)(gp0 + l);
                #pragma unroll
                for (int u = 0; u < VV; u++) ls[u] += (v == u);
            }
        }
    }
    // reduce selected counts: warp shfl -> smem -> 6 threads
    #pragma unroll
    for (int u = 0; u < VV; u++) {
        #pragma unroll
        for (int o = 16; o; o >>= 1) ls[u] += __shfl_down_sync(0xFFFFFFFFu, ls[u], o);
    }
    {
        const int w = tid >> 5, lane = tid & 31;
        if (lane == 0) {
            #pragma unroll
            for (int u = 0; u < VV; u++) wls[w][u] = ls[u];
        }
    }
    __syncthreads();
    if (tid < VV) {
        int s = 0;
        #pragma unroll
        for (int i = 0; i < 8; i++) s += wls[i][tid];
        g_sel[row][ch][tid] = s;
    }
}

// ===========================================================================
// K3: per-row pooling + classifier. 512 blocks x 128 threads.
// ===========================================================================
__global__ void __launch_bounds__(128)
k3_classify(const float* __restrict__ C1, const float* __restrict__ c1,
            const float* __restrict__ C2, const float* __restrict__ c2,
            float* __restrict__ out) {
    const int row = blockIdx.x;
    const int tid = threadIdx.x;

    __shared__ int   selcnt[VV];
    __shared__ float pooled[DD];
    __shared__ float hbuf[64];

    if (tid < VV) {
        int s = 0;
        #pragma unroll
        for (int r = 0; r < CS; r++) s += g_sel[row][r][tid];
        selcnt[tid] = s;
    }
    __syncthreads();

    // pooled = sum_v cnt_v * att_v / K
    {
        float s = 0.f;
        #pragma unroll
        for (int v = 0; v < VV; v++)
            s = fmaf((float)selcnt[v], g_att[v * DD + tid], s);
        pooled[tid] = s / (float)KK;
    }
    __syncthreads();

    if (tid < 64) {
        float s0 = 0.f, s1 = 0.f;
        #pragma unroll
        for (int d = 0; d < DD; d += 2) {
            s0 = fmaf(pooled[d + 0], C1[(d + 0) * 64 + tid], s0);
            s1 = fmaf(pooled[d + 1], C1[(d + 1) * 64 + tid], s1);
        }
        hbuf[tid] = fmaxf(s0 + s1 + c1[tid], 0.f);
    }
    __syncthreads();

    if (tid < 32) {
        float s = fmaf(hbuf[tid], C2[tid], hbuf[tid + 32] * C2[tid + 32]);
        #pragma unroll
        for (int o = 16; o; o >>= 1) s += __shfl_down_sync(0xFFFFFFFFu, s, o);
        if (tid == 0) out[row] = 1.f / (1.f + expf(-(s + c2[0])));
    }
}

// ===========================================================================
// Launch
// ===========================================================================
extern "C" void kernel_launch(void* const* d_in, const int* in_sizes, int n_in,
                              void* d_out, int out_size) {
    const int*   x   = (const int*)  d_in[0];
    const float* emb = (const float*)d_in[1];
    const float* W1  = (const float*)d_in[2];
    const float* b1  = (const float*)d_in[3];
    const float* W2  = (const float*)d_in[4];
    const float* b2  = (const float*)d_in[5];
    const float* W3  = (const float*)d_in[6];
    const float* b3  = (const float*)d_in[7];
    const float* A1  = (const float*)d_in[8];
    const float* a1  = (const float*)d_in[9];
    const float* A2  = (const float*)d_in[10];
    const float* a2  = (const float*)d_in[11];
    const float* C1  = (const float*)d_in[12];
    const float* c1  = (const float*)d_in[13];
    const float* C2  = (const float*)d_in[14];
    const float* c2  = (const float*)d_in[15];
    float* out = (float*)d_out;

    k1_hist_tables<<<BB * CS + 1, NT>>>(x, emb, W1, b1, W2, b2, W3, b3, A1, a1, A2, a2);
    k2_rank<<<BB * CS, NT>>>(x, out);
    k3_classify<<<BB, 128>>>(C1, c1, C2, c2, out);
}

// round 4
// speedup vs baseline: 4.9336x; 1.2452x over previous
#include <cuda_runtime.h>
#include <cstdint>

#define BB 512
#define SS 4096
#define DD 128
#define KK 409
#define VV 6
#define CS 4            // chunks per row
#define CHUNK 1024      // tokens per chunk
#define NT 256

// -------- global scratch (plain overwrites only; deterministic) --------
__device__ int   g_hist[BB][CS][VV];
__device__ int   g_sel [BB][CS][VV];
__device__ float g_sc  [VV];
__device__ float g_att [VV * DD];

// ===========================================================================
// K1: blocks 0..511   -> per-row chunk histograms (packed-counter, coalesced)
//     blocks 512..517 -> score MLP for class (bid-512)
//     blocks 518..523 -> attention MLP for class (bid-518)
// ===========================================================================
__global__ void __launch_bounds__(NT, 4)
k1_hist_tables(const int* __restrict__ x,
               const float* __restrict__ emb,
               const float* __restrict__ W1, const float* __restrict__ b1,
               const float* __restrict__ W2, const float* __restrict__ b2,
               const float* __restrict__ W3, const float* __restrict__ b3,
               const float* __restrict__ A1, const float* __restrict__ a1,
               const float* __restrict__ A2, const float* __restrict__ a2) {
    const int tid = threadIdx.x;

    if (blockIdx.x < BB) {
        // ---------------- histogram CTA (one row) ----------------
        const int row = blockIdx.x;
        const int w = tid >> 5, lane = tid & 31;
        const int ch = w >> 1, half = w & 1;

        const int* base = x + (size_t)row * SS + ch * CHUNK + half * 512 + lane * 4;
        // 4 independent coalesced int4 loads (each warp covers 512B per load)
        const int4 t0 = *reinterpret_cast<const int4*>(base + 0);
        const int4 t1 = *reinterpret_cast<const int4*>(base + 128);
        const int4 t2 = *reinterpret_cast<const int4*>(base + 256);
        const int4 t3 = *reinterpret_cast<const int4*>(base + 384);

        // packed 10-bit-per-class counter (max 512/class per warp: fits)
        unsigned long long c = 0;
        c += 1ULL << (10 * t0.x); c += 1ULL << (10 * t0.y);
        c += 1ULL << (10 * t0.z); c += 1ULL << (10 * t0.w);
        c += 1ULL << (10 * t1.x); c += 1ULL << (10 * t1.y);
        c += 1ULL << (10 * t1.z); c += 1ULL << (10 * t1.w);
        c += 1ULL << (10 * t2.x); c += 1ULL << (10 * t2.y);
        c += 1ULL << (10 * t2.z); c += 1ULL << (10 * t2.w);
        c += 1ULL << (10 * t3.x); c += 1ULL << (10 * t3.y);
        c += 1ULL << (10 * t3.z); c += 1ULL << (10 * t3.w);

        #pragma unroll
        for (int o = 16; o; o >>= 1) c += __shfl_down_sync(0xFFFFFFFFu, c, o);

        __shared__ unsigned long long wred[8];
        if (lane == 0) wred[w] = c;
        __syncthreads();

        if (tid < CS * VV) {
            const int cch = tid / VV, v = tid % VV;
            const unsigned long long a = wred[2 * cch], b = wred[2 * cch + 1];
            g_hist[row][cch][v] = (int)((a >> (10 * v)) & 1023ULL)
                                + (int)((b >> (10 * v)) & 1023ULL);
        }
        return;
    }

    // ---------------- table CTAs ----------------
    const int bid = blockIdx.x - BB;
    __shared__ float e_s[DD];
    __shared__ float h1_s[64];   // also used as g_s for att chain
    __shared__ float h2_s[32];

    const int v = (bid < VV) ? bid : bid - VV;
    if (tid < DD) e_s[tid] = emb[v * DD + tid];
    __syncthreads();

    if (bid < VV) {
        // ======== score chain: e -> h1(64) -> h2(32) -> score ========
        {   // h1: 4 threads per neuron, 8 independent accumulators
            const int n = tid >> 2, q = tid & 3;
            const int i0 = q * 32;
            float acc[8] = {0, 0, 0, 0, 0, 0, 0, 0};
            #pragma unroll
            for (int m = 0; m < 4; m++)
                #pragma unroll
                for (int j = 0; j < 8; j++) {
                    const int i = i0 + m * 8 + j;
                    acc[j] = fmaf(e_s[i], W1[i * 64 + n], acc[j]);
                }
            float s = ((acc[0] + acc[1]) + (acc[2] + acc[3]))
                    + ((acc[4] + acc[5]) + (acc[6] + acc[7]));
            s += __shfl_down_sync(0xFFFFFFFFu, s, 2);
            s += __shfl_down_sync(0xFFFFFFFFu, s, 1);
            if (q == 0) h1_s[n] = fmaxf(s + b1[n], 0.f);
        }
        __syncthreads();
        {   // h2: 8 threads per neuron
            const int n = tid >> 3, r = tid & 7;
            float acc[8];
            #pragma unroll
            for (int j = 0; j < 8; j++) {
                const int i = r + 8 * j;
                acc[j] = h1_s[i] * W2[i * 32 + n];
            }
            float s = ((acc[0] + acc[1]) + (acc[2] + acc[3]))
                    + ((acc[4] + acc[5]) + (acc[6] + acc[7]));
            s += __shfl_down_sync(0xFFFFFFFFu, s, 4);
            s += __shfl_down_sync(0xFFFFFFFFu, s, 2);
            s += __shfl_down_sync(0xFFFFFFFFu, s, 1);
            if (r == 0) h2_s[n] = fmaxf(s + b2[n], 0.f);
        }
        __syncthreads();
        if (tid < 32) {
            float s = h2_s[tid] * W3[tid];
            #pragma unroll
            for (int o = 16; o; o >>= 1) s += __shfl_down_sync(0xFFFFFFFFu, s, o);
            if (tid == 0) g_sc[v] = 1.f / (1.f + expf(-(s + b3[0])));
        }
    } else {
        // ======== attention chain: e -> g(64) -> att(128) ========
        {   // g: 4 threads per neuron
            const int n = tid >> 2, q = tid & 3;
            const int i0 = q * 32;
            float acc[8] = {0, 0, 0, 0, 0, 0, 0, 0};
            #pragma unroll
            for (int m = 0; m < 4; m++)
                #pragma unroll
                for (int j = 0; j < 8; j++) {
                    const int i = i0 + m * 8 + j;
                    acc[j] = fmaf(e_s[i], A1[i * 64 + n], acc[j]);
                }
            float s = ((acc[0] + acc[1]) + (acc[2] + acc[3]))
                    + ((acc[4] + acc[5]) + (acc[6] + acc[7]));
            s += __shfl_down_sync(0xFFFFFFFFu, s, 2);
            s += __shfl_down_sync(0xFFFFFFFFu, s, 1);
            if (q == 0) h1_s[n] = fmaxf(s + a1[n], 0.f);   // g
        }
        __syncthreads();
        {   // att: 2 threads per output dim
            const int d = tid >> 1, q = tid & 1;
            const int j0 = q * 32;
            float acc[8] = {0, 0, 0, 0, 0, 0, 0, 0};
            #pragma unroll
            for (int m = 0; m < 4; m++)
                #pragma unroll
                for (int jj = 0; jj < 8; jj++) {
                    const int j = j0 + m * 8 + jj;
                    acc[jj] = fmaf(h1_s[j], A2[j * DD + d], acc[jj]);
                }
            float s = ((acc[0] + acc[1]) + (acc[2] + acc[3]))
                    + ((acc[4] + acc[5]) + (acc[6] + acc[7]));
            s += __shfl_down_sync(0xFFFFFFFFu, s, 1);
            if (q == 0) g_att[v * DD + d] = s + a2[d];
        }
    }
}

// ===========================================================================
// K2: 2048 chunk-CTAs. fs LUT writes, ranked top-k scatter, sel counts.
// ===========================================================================
__global__ void __launch_bounds__(NT)
k2_rank(const int* __restrict__ x, float* __restrict__ out) {
    const int row = blockIdx.x >> 2, ch = blockIdx.x & 3;
    const int tid = threadIdx.x;

    __shared__ float sc_s[VV];
    __shared__ int   hsm[CS][VV];
    __shared__ int   pref[VV][NT];
    __shared__ int   base_s[VV];
    __shared__ unsigned eqm_s[VV];
    __shared__ int   wls[8][VV];

    float* __restrict__ top_out = out + BB;
    float* __restrict__ fs_out  = out + BB + (size_t)BB * KK;

    // early loads (hidden behind everything before first barrier)
    if (tid < VV) sc_s[tid] = g_sc[tid];
    if (tid >= 192 && tid < 192 + CS * VV)
        hsm[(tid - 192) / VV][(tid - 192) % VV] = g_hist[row][(tid - 192) / VV][(tid - 192) % VV];

    const int4 tv = *reinterpret_cast<const int4*>(
        x + (size_t)row * SS + (size_t)ch * CHUNK + (size_t)tid * 4);
    const int tok[4] = {tv.x, tv.y, tv.z, tv.w};

    #pragma unroll
    for (int u = 0; u < VV; u++) {
        int c = 0;
        #pragma unroll
        for (int l = 0; l < 4; l++) c += (tok[l] == u);
        pref[u][tid] = c;
    }
    __syncthreads();

    // fs writes (all warps) — sc_s is now visible
    {
        float4 f;
        f.x = sc_s[tok[0]]; f.y = sc_s[tok[1]]; f.z = sc_s[tok[2]]; f.w = sc_s[tok[3]];
        *reinterpret_cast<float4*>(fs_out + (size_t)row * SS + (size_t)ch * CHUNK
                                   + (size_t)tid * 4) = f;
    }

    // warps 0-5: scan class w over 256 chunks; warp 6: base/eqm from smem
    {
        const int w = tid >> 5, lane = tid & 31;
        if (w < VV) {
            int vals[8]; int sum = 0;
            #pragma unroll
            for (int i = 0; i < 8; i++) { vals[i] = pref[w][lane * 8 + i]; sum += vals[i]; }
            int incl = sum;
            #pragma unroll
            for (int off = 1; off < 32; off <<= 1) {
                int n = __shfl_up_sync(0xFFFFFFFFu, incl, off);
                if (lane >= off) incl += n;
            }
            int excl = incl - sum;
            #pragma unroll
            for (int i = 0; i < 8; i++) { const int t = vals[i]; pref[w][lane * 8 + i] = excl; excl += t; }
        } else if (w == 6 && lane < VV) {
            const float sv = sc_s[lane];
            int b = 0; unsigned m = 0;
            #pragma unroll
            for (int u = 0; u < VV; u++) {
                const float su = sc_s[u];
                const int tu = hsm[0][u] + hsm[1][u] + hsm[2][u] + hsm[3][u];
                if (su > sv) b += tu;
                if (su == sv) {
                    m |= 1u << u;
                    for (int r = 0; r < ch; r++) b += hsm[r][u];
                }
            }
            base_s[lane] = b; eqm_s[lane] = m;
        }
    }
    __syncthreads();

    // ranked scatter + selected counts
    int ls[VV] = {0, 0, 0, 0, 0, 0};
    {
        int P[VV];
        #pragma unroll
        for (int u = 0; u < VV; u++) P[u] = pref[u][tid];
        int rc[VV] = {0, 0, 0, 0, 0, 0};
        const size_t obase = (size_t)row * KK;
        const int gp0 = ch * CHUNK + tid * 4;
        #pragma unroll
        for (int l = 0; l < 4; l++) {
            const int v = tok[l];
            const unsigned m = eqm_s[v];
            int r = base_s[v];
            #pragma unroll
            for (int u = 0; u < VV; u++)
                if ((m >> u) & 1u) r += P[u] + rc[u];
            #pragma unroll
            for (int u = 0; u < VV; u++) rc[u] += (v == u);
            if (r < KK) {
                top_out[obase + r] = (float)(gp0 + l);
                #pragma unroll
                for (int u = 0; u < VV; u++) ls[u] += (v == u);
            }
        }
    }
    #pragma unroll
    for (int u = 0; u < VV; u++) {
        #pragma unroll
        for (int o = 16; o; o >>= 1) ls[u] += __shfl_down_sync(0xFFFFFFFFu, ls[u], o);
    }
    {
        const int w = tid >> 5, lane = tid & 31;
        if (lane == 0) {
            #pragma unroll
            for (int u = 0; u < VV; u++) wls[w][u] = ls[u];
        }
    }
    __syncthreads();
    if (tid < VV) {
        int s = 0;
        #pragma unroll
        for (int i = 0; i < 8; i++) s += wls[i][tid];
        g_sel[row][ch][tid] = s;
    }
}

// ===========================================================================
// K3: per-row pooling + classifier.
// ===========================================================================
__global__ void __launch_bounds__(128)
k3_classify(const float* __restrict__ C1, const float* __restrict__ c1,
            const float* __restrict__ C2, const float* __restrict__ c2,
            float* __restrict__ out) {
    const int row = blockIdx.x;
    const int tid = threadIdx.x;

    __shared__ int   selcnt[VV];
    __shared__ float pooled[DD];
    __shared__ float hbuf[64];

    if (tid < VV) {
        int s = 0;
        #pragma unroll
        for (int r = 0; r < CS; r++) s += g_sel[row][r][tid];
        selcnt[tid] = s;
    }
    __syncthreads();

    {
        float s = 0.f;
        #pragma unroll
        for (int v = 0; v < VV; v++)
            s = fmaf((float)selcnt[v], g_att[v * DD + tid], s);
        pooled[tid] = s / (float)KK;
    }
    __syncthreads();

    if (tid < 64) {
        float s0 = 0.f, s1 = 0.f;
        #pragma unroll
        for (int d = 0; d < DD; d += 2) {
            s0 = fmaf(pooled[d + 0], C1[(d + 0) * 64 + tid], s0);
            s1 = fmaf(pooled[d + 1], C1[(d + 1) * 64 + tid], s1);
        }
        hbuf[tid] = fmaxf(s0 + s1 + c1[tid], 0.f);
    }
    __syncthreads();

    if (tid < 32) {
        float s = fmaf(hbuf[tid], C2[tid], hbuf[tid + 32] * C2[tid + 32]);
        #pragma unroll
        for (int o = 16; o; o >>= 1) s += __shfl_down_sync(0xFFFFFFFFu, s, o);
        if (tid == 0) out[row] = 1.f / (1.f + expf(-(s + c2[0])));
    }
}

// ===========================================================================
extern "C" void kernel_launch(void* const* d_in, const int* in_sizes, int n_in,
                              void* d_out, int out_size) {
    const int*   x   = (const int*)  d_in[0];
    const float* emb = (const float*)d_in[1];
    const float* W1  = (const float*)d_in[2];
    const float* b1  = (const float*)d_in[3];
    const float* W2  = (const float*)d_in[4];
    const float* b2  = (const float*)d_in[5];
    const float* W3  = (const float*)d_in[6];
    const float* b3  = (const float*)d_in[7];
    const float* A1  = (const float*)d_in[8];
    const float* a1  = (const float*)d_in[9];
    const float* A2  = (const float*)d_in[10];
    const float* a2  = (const float*)d_in[11];
    const float* C1  = (const float*)d_in[12];
    const float* c1  = (const float*)d_in[13];
    const float* C2  = (const float*)d_in[14];
    const float* c2  = (const float*)d_in[15];
    float* out = (float*)d_out;

    k1_hist_tables<<<BB + 2 * VV, NT>>>(x, emb, W1, b1, W2, b2, W3, b3, A1, a1, A2, a2);
    k2_rank<<<BB * CS, NT>>>(x, out);
    k3_classify<<<BB, 128>>>(C1, c1, C2, c2, out);
}